// round 1
// baseline (speedup 1.0000x reference)
#include <cuda_runtime.h>

// Problem constants
#define TBv 16          // T*B
#define Nv  1024
#define Dv  512
#define Hv  8
#define HDv 64
#define Mv  (TBv * Nv)  // 16384 tokens

// Scratch: q,k,v head-major [TB][H][N][HD]; ctx token-major [M][D]
__device__ float g_q[TBv * Hv * Nv * HDv];
__device__ float g_k[TBv * Hv * Nv * HDv];
__device__ float g_v[TBv * Hv * Nv * HDv];
__device__ float g_ctx[(size_t)Mv * Dv];

// ---------------------------------------------------------------------------
// Fused QKV projection: y = x @ W^T + b for wq|wk|wv (N-dim = 1536 concat).
// 128x128 block tile, K-step 16, 256 threads, 8x8 microtile.
// Writes q/k/v directly in head-major layout.
// ---------------------------------------------------------------------------
__global__ __launch_bounds__(256) void qkv_gemm(
    const float* __restrict__ x,
    const float* __restrict__ wq, const float* __restrict__ bq,
    const float* __restrict__ wk, const float* __restrict__ bk,
    const float* __restrict__ wv, const float* __restrict__ bv)
{
    __shared__ float As[16][132];
    __shared__ float Bs[16][132];

    const int m0  = blockIdx.x * 128;
    const int j0g = blockIdx.y * 128;      // 0..1535
    const int wsel = j0g >> 9;             // 0:q 1:k 2:v
    const int j0   = j0g & 511;

    const float* __restrict__ w    = (wsel == 0) ? wq : (wsel == 1) ? wk : wv;
    const float* __restrict__ bias = (wsel == 0) ? bq : (wsel == 1) ? bk : bv;
    float* __restrict__ obuf       = (wsel == 0) ? g_q : (wsel == 1) ? g_k : g_v;

    const int tid = threadIdx.x;
    const int tx = tid & 15;      // m microtile (8 rows)
    const int ty = tid >> 4;      // j microtile (8 cols)
    const int lr = tid >> 2;      // loader row 0..63
    const int lc = (tid & 3) * 4; // loader col 0,4,8,12

    float acc[8][8];
#pragma unroll
    for (int i = 0; i < 8; i++)
#pragma unroll
        for (int j = 0; j < 8; j++) acc[i][j] = 0.f;

    for (int k0 = 0; k0 < Dv; k0 += 16) {
#pragma unroll
        for (int hh = 0; hh < 2; ++hh) {
            const int r = lr + hh * 64;
            float4 va = *(const float4*)&x[(size_t)(m0 + r) * Dv + k0 + lc];
            As[lc + 0][r] = va.x; As[lc + 1][r] = va.y;
            As[lc + 2][r] = va.z; As[lc + 3][r] = va.w;
            float4 vb = *(const float4*)&w[(size_t)(j0 + r) * Dv + k0 + lc];
            Bs[lc + 0][r] = vb.x; Bs[lc + 1][r] = vb.y;
            Bs[lc + 2][r] = vb.z; Bs[lc + 3][r] = vb.w;
        }
        __syncthreads();
#pragma unroll
        for (int kk = 0; kk < 16; ++kk) {
            float a[8], b[8];
            *(float4*)&a[0] = *(const float4*)&As[kk][tx * 8];
            *(float4*)&a[4] = *(const float4*)&As[kk][tx * 8 + 4];
            *(float4*)&b[0] = *(const float4*)&Bs[kk][ty * 8];
            *(float4*)&b[4] = *(const float4*)&Bs[kk][ty * 8 + 4];
#pragma unroll
            for (int i = 0; i < 8; i++)
#pragma unroll
                for (int j = 0; j < 8; j++) acc[i][j] += a[i] * b[j];
        }
        __syncthreads();
    }

    // Epilogue: bias add, scatter to head-major q/k/v
    float bb[8];
#pragma unroll
    for (int j = 0; j < 8; j++) bb[j] = bias[j0 + ty * 8 + j];
    const int col0 = j0 + ty * 8;   // ty*8 is 8-aligned -> never crosses a head
    const int h   = col0 >> 6;
    const int hd0 = col0 & 63;
#pragma unroll
    for (int i = 0; i < 8; i++) {
        const int m  = m0 + tx * 8 + i;
        const int tb = m >> 10;
        const int n  = m & 1023;
        float* dst = &obuf[((size_t)(tb * Hv + h) * Nv + n) * HDv + hd0];
        *(float4*)&dst[0] = make_float4(acc[i][0] + bb[0], acc[i][1] + bb[1],
                                        acc[i][2] + bb[2], acc[i][3] + bb[3]);
        *(float4*)&dst[4] = make_float4(acc[i][4] + bb[4], acc[i][5] + bb[5],
                                        acc[i][6] + bb[6], acc[i][7] + bb[7]);
    }
}

// ---------------------------------------------------------------------------
// One-pass relu-normalized attention.
// Block: 128 q-rows of one (tb,h). Loop over 16 K/V tiles of 64 rows.
//   stage1: S = relu(Q K^T / 8) into smem (transposed), accumulate row sums
//   stage2: acc += S V
// Final: ctx = acc / (rowsum + eps), written token-major for the out GEMM.
// Dynamic smem: Qs[64][132] + Ss[64][132] + KV[64][68] = 84992 B.
// ---------------------------------------------------------------------------
#define ATTN_SMEM_BYTES ((2 * 64 * 132 + 64 * 68) * 4)

__global__ __launch_bounds__(256) void attn_kernel()
{
    extern __shared__ float smem[];
    float* Qs = smem;                 // [hd][q]  stride 132
    float* Ss = smem + 64 * 132;      // [kc][q]  stride 132
    float* KV = smem + 2 * 64 * 132;  // [64][68] : K^T (hd-major) then V (kc-major)

    const int tid = threadIdx.x;
    const int tx = tid & 15;          // q microtile (8 rows)
    const int ty = tid >> 4;          // 4 k-cols (stage1) / 4 hd-cols (stage2)
    const int qt  = blockIdx.x;       // 0..7
    const int tbh = blockIdx.y;       // 0..127
    const int qn0 = qt * 128;

    const float* __restrict__ qptr = &g_q[(size_t)tbh * Nv * HDv];
    const float* __restrict__ kptr = &g_k[(size_t)tbh * Nv * HDv];
    const float* __restrict__ vptr = &g_v[(size_t)tbh * Nv * HDv];

    // Load Q tile transposed: Qs[hd][q]
    {
        const int qr  = tid >> 1;
        const int hd0 = (tid & 1) * 32;
        const float* src = &qptr[(size_t)(qn0 + qr) * HDv + hd0];
#pragma unroll
        for (int u = 0; u < 8; ++u) {
            float4 v = *(const float4*)&src[u * 4];
            Qs[(hd0 + u * 4 + 0) * 132 + qr] = v.x;
            Qs[(hd0 + u * 4 + 1) * 132 + qr] = v.y;
            Qs[(hd0 + u * 4 + 2) * 132 + qr] = v.z;
            Qs[(hd0 + u * 4 + 3) * 132 + qr] = v.w;
        }
    }

    float acc[8][4];
    float dsum[8];
#pragma unroll
    for (int i = 0; i < 8; i++) {
        dsum[i] = 0.f;
#pragma unroll
        for (int j = 0; j < 4; j++) acc[i][j] = 0.f;
    }

    const int lkc = tid >> 2;          // 0..63
    const int lhd = (tid & 3) * 16;
    __syncthreads();

    for (int kt = 0; kt < Nv / 64; ++kt) {
        // Load K tile transposed: KV[hd][kc]
        {
            const float* src = &kptr[(size_t)(kt * 64 + lkc) * HDv + lhd];
#pragma unroll
            for (int u = 0; u < 4; ++u) {
                float4 v = *(const float4*)&src[u * 4];
                KV[(lhd + u * 4 + 0) * 68 + lkc] = v.x;
                KV[(lhd + u * 4 + 1) * 68 + lkc] = v.y;
                KV[(lhd + u * 4 + 2) * 68 + lkc] = v.z;
                KV[(lhd + u * 4 + 3) * 68 + lkc] = v.w;
            }
        }
        __syncthreads();

        // stage1: S = Q K^T
        float s[8][4];
#pragma unroll
        for (int i = 0; i < 8; i++)
#pragma unroll
            for (int j = 0; j < 4; j++) s[i][j] = 0.f;
#pragma unroll 4
        for (int hd = 0; hd < 64; ++hd) {
            float a[8], b[4];
            *(float4*)&a[0] = *(const float4*)&Qs[hd * 132 + tx * 8];
            *(float4*)&a[4] = *(const float4*)&Qs[hd * 132 + tx * 8 + 4];
            *(float4*)&b[0] = *(const float4*)&KV[hd * 68 + ty * 4];
#pragma unroll
            for (int i = 0; i < 8; i++)
#pragma unroll
                for (int j = 0; j < 4; j++) s[i][j] += a[i] * b[j];
        }
        // scale + relu + rowsum partials; store S transposed: Ss[kc][q]
#pragma unroll
        for (int j = 0; j < 4; ++j) {
            float t[8];
#pragma unroll
            for (int i = 0; i < 8; ++i) {
                float v = s[i][j] * 0.125f;
                v = v > 0.f ? v : 0.f;
                dsum[i] += v;
                t[i] = v;
            }
            float* dst = &Ss[(ty * 4 + j) * 132 + tx * 8];
            *(float4*)&dst[0] = make_float4(t[0], t[1], t[2], t[3]);
            *(float4*)&dst[4] = make_float4(t[4], t[5], t[6], t[7]);
        }
        __syncthreads();

        // Load V tile natural: KV[kc][hd] (overwrites K^T)
        {
            const float* src = &vptr[(size_t)(kt * 64 + lkc) * HDv + lhd];
#pragma unroll
            for (int u = 0; u < 4; ++u) {
                float4 v = *(const float4*)&src[u * 4];
                *(float4*)&KV[lkc * 68 + lhd + u * 4] = v;
            }
        }
        __syncthreads();

        // stage2: acc += S V
#pragma unroll 4
        for (int kk = 0; kk < 64; ++kk) {
            float a[8], b[4];
            *(float4*)&a[0] = *(const float4*)&Ss[kk * 132 + tx * 8];
            *(float4*)&a[4] = *(const float4*)&Ss[kk * 132 + tx * 8 + 4];
            *(float4*)&b[0] = *(const float4*)&KV[kk * 68 + ty * 4];
#pragma unroll
            for (int i = 0; i < 8; i++)
#pragma unroll
                for (int j = 0; j < 4; j++) acc[i][j] += a[i] * b[j];
        }
        __syncthreads();
    }

    // Row-sum reduction across ty (reuse KV as dred[16][128])
    float* dred = KV;
#pragma unroll
    for (int i = 0; i < 8; ++i) dred[ty * 128 + tx * 8 + i] = dsum[i];
    __syncthreads();

    const int tb = tbh >> 3;
    const int h  = tbh & 7;
#pragma unroll
    for (int i = 0; i < 8; ++i) {
        const int q = tx * 8 + i;
        float den = 0.f;
#pragma unroll
        for (int t = 0; t < 16; ++t) den += dred[t * 128 + q];
        const float inv = 1.f / (den + 1e-6f);
        const size_t m = (size_t)tb * Nv + qn0 + q;
        float* dst = &g_ctx[m * Dv + h * HDv + ty * 4];
        *(float4*)dst = make_float4(acc[i][0] * inv, acc[i][1] * inv,
                                    acc[i][2] * inv, acc[i][3] * inv);
    }
}

// ---------------------------------------------------------------------------
// Output projection: out = ctx @ wo^T + bo. Same 128x128/8x8 GEMM structure.
// ---------------------------------------------------------------------------
__global__ __launch_bounds__(256) void out_gemm(
    const float* __restrict__ wo, const float* __restrict__ bo,
    float* __restrict__ out)
{
    __shared__ float As[16][132];
    __shared__ float Bs[16][132];

    const int m0 = blockIdx.x * 128;
    const int j0 = blockIdx.y * 128;   // 0..511

    const int tid = threadIdx.x;
    const int tx = tid & 15;
    const int ty = tid >> 4;
    const int lr = tid >> 2;
    const int lc = (tid & 3) * 4;

    float acc[8][8];
#pragma unroll
    for (int i = 0; i < 8; i++)
#pragma unroll
        for (int j = 0; j < 8; j++) acc[i][j] = 0.f;

    for (int k0 = 0; k0 < Dv; k0 += 16) {
#pragma unroll
        for (int hh = 0; hh < 2; ++hh) {
            const int r = lr + hh * 64;
            float4 va = *(const float4*)&g_ctx[(size_t)(m0 + r) * Dv + k0 + lc];
            As[lc + 0][r] = va.x; As[lc + 1][r] = va.y;
            As[lc + 2][r] = va.z; As[lc + 3][r] = va.w;
            float4 vb = *(const float4*)&wo[(size_t)(j0 + r) * Dv + k0 + lc];
            Bs[lc + 0][r] = vb.x; Bs[lc + 1][r] = vb.y;
            Bs[lc + 2][r] = vb.z; Bs[lc + 3][r] = vb.w;
        }
        __syncthreads();
#pragma unroll
        for (int kk = 0; kk < 16; ++kk) {
            float a[8], b[8];
            *(float4*)&a[0] = *(const float4*)&As[kk][tx * 8];
            *(float4*)&a[4] = *(const float4*)&As[kk][tx * 8 + 4];
            *(float4*)&b[0] = *(const float4*)&Bs[kk][ty * 8];
            *(float4*)&b[4] = *(const float4*)&Bs[kk][ty * 8 + 4];
#pragma unroll
            for (int i = 0; i < 8; i++)
#pragma unroll
                for (int j = 0; j < 8; j++) acc[i][j] += a[i] * b[j];
        }
        __syncthreads();
    }

    float bb[8];
#pragma unroll
    for (int j = 0; j < 8; j++) bb[j] = bo[j0 + ty * 8 + j];
#pragma unroll
    for (int i = 0; i < 8; i++) {
        const int m = m0 + tx * 8 + i;
        float* dst = &out[(size_t)m * Dv + j0 + ty * 8];
        *(float4*)&dst[0] = make_float4(acc[i][0] + bb[0], acc[i][1] + bb[1],
                                        acc[i][2] + bb[2], acc[i][3] + bb[3]);
        *(float4*)&dst[4] = make_float4(acc[i][4] + bb[4], acc[i][5] + bb[5],
                                        acc[i][6] + bb[6], acc[i][7] + bb[7]);
    }
}

// ---------------------------------------------------------------------------
extern "C" void kernel_launch(void* const* d_in, const int* in_sizes, int n_in,
                              void* d_out, int out_size)
{
    const float* x  = (const float*)d_in[0];
    const float* wq = (const float*)d_in[1];
    const float* bq = (const float*)d_in[2];
    const float* wk = (const float*)d_in[3];
    const float* bk = (const float*)d_in[4];
    const float* wv = (const float*)d_in[5];
    const float* bv = (const float*)d_in[6];
    const float* wo = (const float*)d_in[7];
    const float* bo = (const float*)d_in[8];
    float* out = (float*)d_out;

    cudaFuncSetAttribute(attn_kernel,
                         cudaFuncAttributeMaxDynamicSharedMemorySize,
                         ATTN_SMEM_BYTES);

    qkv_gemm<<<dim3(Mv / 128, 12), 256>>>(x, wq, bq, wk, bk, wv, bv);
    attn_kernel<<<dim3(Nv / 128, TBv * Hv), 256, ATTN_SMEM_BYTES>>>();
    out_gemm<<<dim3(Mv / 128, Dv / 128), 256>>>(wo, bo, out);
}

// round 3
// speedup vs baseline: 1.2553x; 1.2553x over previous
#include <cuda_runtime.h>
#include <mma.h>
#include <cstdint>

using namespace nvcuda;

// Problem constants
#define TBv 16          // T*B
#define Nv  1024
#define Dv  512
#define Hv  8
#define HDv 64
#define Mv  (TBv * Nv)  // 16384 tokens

// Scratch: q,k,v head-major [TB][H][N][HD]; ctx token-major [M][D]
__device__ float g_q[TBv * Hv * Nv * HDv];
__device__ float g_k[TBv * Hv * Nv * HDv];
__device__ float g_v[TBv * Hv * Nv * HDv];
__device__ float g_ctx[(size_t)Mv * Dv];

// ---------------------------------------------------------------------------
// tf32 helpers (3xTF32 split: x = hi + lo, products exact in fp32 accum)
// ---------------------------------------------------------------------------
__device__ __forceinline__ float tf32_rna(float x) {
    uint32_t r;
    asm("cvt.rna.tf32.f32 %0, %1;" : "=r"(r) : "f"(x));
    return __uint_as_float(r);
}

__device__ __forceinline__ void split4(float4 v, float4& h, float4& l) {
    h.x = tf32_rna(v.x); l.x = tf32_rna(v.x - h.x);
    h.y = tf32_rna(v.y); l.y = tf32_rna(v.y - h.y);
    h.z = tf32_rna(v.z); l.z = tf32_rna(v.z - h.z);
    h.w = tf32_rna(v.w); l.w = tf32_rna(v.w - h.w);
}

using FragA  = wmma::fragment<wmma::matrix_a, 16, 16, 8, wmma::precision::tf32, wmma::row_major>;
using FragBc = wmma::fragment<wmma::matrix_b, 16, 16, 8, wmma::precision::tf32, wmma::col_major>;
using FragBr = wmma::fragment<wmma::matrix_b, 16, 16, 8, wmma::precision::tf32, wmma::row_major>;
using FragC  = wmma::fragment<wmma::accumulator, 16, 16, 8, float>;

// ===========================================================================
// GEMM: D[128x128] = A[128xK=512] . B[128 rows x 512]^T (+ bias via extra K)
// 128 threads, 4 warps (2x2), warp tile 64x64 = 4x4 m16n16k8 frags.
// K-chunk 16 (2 ksteps), smem planes hi/lo for A and B, stride 20.
// ===========================================================================
#define GS 20
#define A_HI 0
#define A_LO (128 * GS)
#define B_HI (2 * 128 * GS)
#define B_LO (3 * 128 * GS)
#define GEMM_SMEM_BYTES (4 * 128 * GS * 4)   // 40960

__device__ __forceinline__ void gemm_kstep(const float* __restrict__ sm,
                                           int ks, int wm, int wn,
                                           FragC (&acc)[4][4])
{
    FragA ahi[4], alo[4];
#pragma unroll
    for (int i = 0; i < 4; ++i) {
        wmma::load_matrix_sync(ahi[i], sm + A_HI + (wm + 16 * i) * GS + ks * 8, GS);
        wmma::load_matrix_sync(alo[i], sm + A_LO + (wm + 16 * i) * GS + ks * 8, GS);
    }
#pragma unroll
    for (int j = 0; j < 4; ++j) {
        FragBc bhi, blo;
        wmma::load_matrix_sync(bhi, sm + B_HI + (wn + 16 * j) * GS + ks * 8, GS);
        wmma::load_matrix_sync(blo, sm + B_LO + (wn + 16 * j) * GS + ks * 8, GS);
#pragma unroll
        for (int i = 0; i < 4; ++i) {
            wmma::mma_sync(acc[i][j], ahi[i], bhi, acc[i][j]);
            wmma::mma_sync(acc[i][j], ahi[i], blo, acc[i][j]);
            wmma::mma_sync(acc[i][j], alo[i], bhi, acc[i][j]);
        }
    }
}

__device__ __forceinline__ void gemm_block_tc(
    const float* __restrict__ Ag,    // block's 128 A rows, row-major stride 512
    const float* __restrict__ Bg,    // block's 128 W rows, row-major stride 512
    const float* __restrict__ bias,  // block's 128 bias entries
    float* __restrict__ sm, FragC (&acc)[4][4])
{
    const int tid = threadIdx.x;
    const int wid = tid >> 5;
    const int wm = (wid & 1) * 64;
    const int wn = (wid >> 1) * 64;
    const int r0 = tid >> 2;          // 0..31
    const int c4 = (tid & 3) * 4;     // 0,4,8,12

#pragma unroll
    for (int i = 0; i < 4; ++i)
#pragma unroll
        for (int j = 0; j < 4; ++j)
            wmma::fill_fragment(acc[i][j], 0.0f);

    for (int ch = 0; ch < 32; ++ch) {
        const int k0 = ch * 16;
        float4 ra[4], rb[4];
#pragma unroll
        for (int u = 0; u < 4; ++u) {
            ra[u] = *(const float4*)&Ag[(size_t)(r0 + 32 * u) * Dv + k0 + c4];
            rb[u] = *(const float4*)&Bg[(size_t)(r0 + 32 * u) * Dv + k0 + c4];
        }
        __syncthreads();   // previous chunk's mma reads done
#pragma unroll
        for (int u = 0; u < 4; ++u) {
            float4 h, l;
            const int rr = (r0 + 32 * u) * GS + c4;
            split4(ra[u], h, l);
            *(float4*)&sm[A_HI + rr] = h;
            *(float4*)&sm[A_LO + rr] = l;
            split4(rb[u], h, l);
            *(float4*)&sm[B_HI + rr] = h;
            *(float4*)&sm[B_LO + rr] = l;
        }
        __syncthreads();
        gemm_kstep(sm, 0, wm, wn, acc);
        gemm_kstep(sm, 1, wm, wn, acc);
    }

    // Bias as one extra K-step: A col0 = 1, B col0 = bias (hi/lo)
    __syncthreads();
    {
        const float bv = bias[tid];
        const float bh = tf32_rna(bv);
        const float bl = tf32_rna(bv - bh);
        const float4 z = make_float4(0.f, 0.f, 0.f, 0.f);
        *(float4*)&sm[A_HI + tid * GS + 0] = make_float4(1.f, 0.f, 0.f, 0.f);
        *(float4*)&sm[A_HI + tid * GS + 4] = z;
        *(float4*)&sm[A_LO + tid * GS + 0] = z;
        *(float4*)&sm[A_LO + tid * GS + 4] = z;
        *(float4*)&sm[B_HI + tid * GS + 0] = make_float4(bh, 0.f, 0.f, 0.f);
        *(float4*)&sm[B_HI + tid * GS + 4] = z;
        *(float4*)&sm[B_LO + tid * GS + 0] = make_float4(bl, 0.f, 0.f, 0.f);
        *(float4*)&sm[B_LO + tid * GS + 4] = z;
    }
    __syncthreads();
    gemm_kstep(sm, 0, wm, wn, acc);
}

// ---------------------------------------------------------------------------
// QKV projection. grid (128, 12): y -> wsel(q/k/v) x 4 col-tiles of 128.
// Stores directly to head-major g_q/g_k/g_v via store_matrix_sync (ldm 64).
// ---------------------------------------------------------------------------
__global__ __launch_bounds__(128) void qkv_gemm_w(
    const float* __restrict__ x,
    const float* __restrict__ wq, const float* __restrict__ bq,
    const float* __restrict__ wk, const float* __restrict__ bk,
    const float* __restrict__ wv, const float* __restrict__ bv)
{
    extern __shared__ float sm[];
    const int m0   = blockIdx.x * 128;
    const int wsel = blockIdx.y >> 2;
    const int n0   = (blockIdx.y & 3) * 128;

    const float* __restrict__ w    = (wsel == 0) ? wq : (wsel == 1) ? wk : wv;
    const float* __restrict__ bias = (wsel == 0) ? bq : (wsel == 1) ? bk : bv;
    float* __restrict__ obuf       = (wsel == 0) ? g_q : (wsel == 1) ? g_k : g_v;

    FragC acc[4][4];
    gemm_block_tc(x + (size_t)m0 * Dv, w + (size_t)n0 * Dv, bias + n0, sm, acc);

    const int wid = threadIdx.x >> 5;
    const int wm = (wid & 1) * 64;
    const int wn = (wid >> 1) * 64;
#pragma unroll
    for (int i = 0; i < 4; ++i) {
        const int m  = m0 + wm + 16 * i;
        const int tb = m >> 10;
        const int n  = m & 1023;
#pragma unroll
        for (int j = 0; j < 4; ++j) {
            const int col = n0 + wn + 16 * j;   // 16-col frag never crosses a head
            const int h   = col >> 6;
            const int hd0 = col & 63;
            wmma::store_matrix_sync(
                &obuf[((size_t)(tb * Hv + h) * Nv + n) * HDv + hd0],
                acc[i][j], HDv, wmma::mem_row_major);
        }
    }
}

// ---------------------------------------------------------------------------
// Output projection: out = ctx @ wo^T + bo. grid (128, 4).
// ---------------------------------------------------------------------------
__global__ __launch_bounds__(128) void out_gemm_w(
    const float* __restrict__ wo, const float* __restrict__ bo,
    float* __restrict__ out)
{
    extern __shared__ float sm[];
    const int m0 = blockIdx.x * 128;
    const int n0 = blockIdx.y * 128;

    FragC acc[4][4];
    gemm_block_tc(g_ctx + (size_t)m0 * Dv, wo + (size_t)n0 * Dv, bo + n0, sm, acc);

    const int wid = threadIdx.x >> 5;
    const int wm = (wid & 1) * 64;
    const int wn = (wid >> 1) * 64;
#pragma unroll
    for (int i = 0; i < 4; ++i)
#pragma unroll
        for (int j = 0; j < 4; ++j)
            wmma::store_matrix_sync(
                &out[(size_t)(m0 + wm + 16 * i) * Dv + n0 + wn + 16 * j],
                acc[i][j], Dv, wmma::mem_row_major);
}

// ===========================================================================
// Attention via tf32 wmma (3xTF32 everywhere).
// Block: 128 q-rows of one (tb,h); 256 threads, 8 warps (4x2), warp 32x32.
// Loop 16 key-tiles of 64: S = QK^T (mma) -> relu/scale + rowsum -> hi/lo
// -> ctx += S V (mma). Final: ctx / (rowsum + eps) -> g_ctx token-major.
// ===========================================================================
#define AS 68
#define QHI 0
#define QLO (128 * AS)            // 8704
#define KHI (2 * 128 * AS)        // 17408
#define KLO (KHI + 64 * AS)
#define VHI (KHI + 2 * 64 * AS)
#define VLO (KHI + 3 * 64 * AS)
#define SHI (KHI + 4 * 64 * AS)   // 34816
#define SLO (SHI + 128 * AS)
#define DSO (SHI + 2 * 128 * AS)  // 52224
#define ATTN_SMEM_BYTES ((DSO + 256) * 4)   // 209920

__global__ __launch_bounds__(256) void attn_w()
{
    extern __shared__ float sm[];
    const int t = threadIdx.x;
    const int w = t >> 5;
    const int wm = (w >> 1) * 32;
    const int wn = (w & 1) * 32;
    const int qt  = blockIdx.x;
    const int tbh = blockIdx.y;
    const int qn0 = qt * 128;

    const float* __restrict__ qg = g_q + (size_t)tbh * Nv * HDv;
    const float* __restrict__ kg = g_k + (size_t)tbh * Nv * HDv;
    const float* __restrict__ vg = g_v + (size_t)tbh * Nv * HDv;

    // Load Q tile 128x64 -> hi/lo planes
    {
        const int row = t >> 1;
        const int c0  = (t & 1) * 32;
        const float* src = qg + (size_t)(qn0 + row) * HDv + c0;
#pragma unroll
        for (int u = 0; u < 8; ++u) {
            float4 v = *(const float4*)&src[u * 4];
            float4 h, l;
            split4(v, h, l);
            *(float4*)&sm[QHI + row * AS + c0 + 4 * u] = h;
            *(float4*)&sm[QLO + row * AS + c0 + 4 * u] = l;
        }
    }

    FragC ctx[2][2];
#pragma unroll
    for (int i = 0; i < 2; ++i)
#pragma unroll
        for (int j = 0; j < 2; ++j)
            wmma::fill_fragment(ctx[i][j], 0.0f);
    float dsum = 0.f;

    const int kr = t >> 2;            // 0..63
    const int kc = (t & 3) * 16;

    for (int kt = 0; kt < 16; ++kt) {
        // stage K and V tiles (64x64) in registers (overlaps prev SV-mma)
        float4 kreg[4], vreg[4];
        {
            const float* ksrc = kg + (size_t)(kt * 64 + kr) * HDv + kc;
            const float* vsrc = vg + (size_t)(kt * 64 + kr) * HDv + kc;
#pragma unroll
            for (int u = 0; u < 4; ++u) {
                kreg[u] = *(const float4*)&ksrc[4 * u];
                vreg[u] = *(const float4*)&vsrc[4 * u];
            }
        }
        __syncthreads();   // (A) prev SV-mma smem reads done; Q visible (it=0)
#pragma unroll
        for (int u = 0; u < 4; ++u) {
            float4 h, l;
            split4(kreg[u], h, l);
            *(float4*)&sm[KHI + kr * AS + kc + 4 * u] = h;
            *(float4*)&sm[KLO + kr * AS + kc + 4 * u] = l;
        }
        __syncthreads();   // (B) K ready

        // S = Q K^T  (3xTF32), warp tile 32x32
        FragC sacc[2][2];
#pragma unroll
        for (int i = 0; i < 2; ++i)
#pragma unroll
            for (int j = 0; j < 2; ++j)
                wmma::fill_fragment(sacc[i][j], 0.0f);
#pragma unroll
        for (int ks = 0; ks < 8; ++ks) {
            FragA qhi[2], qlo[2];
#pragma unroll
            for (int i = 0; i < 2; ++i) {
                wmma::load_matrix_sync(qhi[i], sm + QHI + (wm + 16 * i) * AS + ks * 8, AS);
                wmma::load_matrix_sync(qlo[i], sm + QLO + (wm + 16 * i) * AS + ks * 8, AS);
            }
#pragma unroll
            for (int j = 0; j < 2; ++j) {
                FragBc khi, klo;
                wmma::load_matrix_sync(khi, sm + KHI + (wn + 16 * j) * AS + ks * 8, AS);
                wmma::load_matrix_sync(klo, sm + KLO + (wn + 16 * j) * AS + ks * 8, AS);
#pragma unroll
                for (int i = 0; i < 2; ++i) {
                    wmma::mma_sync(sacc[i][j], qhi[i], khi, sacc[i][j]);
                    wmma::mma_sync(sacc[i][j], qhi[i], klo, sacc[i][j]);
                    wmma::mma_sync(sacc[i][j], qlo[i], khi, sacc[i][j]);
                }
            }
        }
#pragma unroll
        for (int i = 0; i < 2; ++i)
#pragma unroll
            for (int j = 0; j < 2; ++j)
                wmma::store_matrix_sync(&sm[SHI + (wm + 16 * i) * AS + wn + 16 * j],
                                        sacc[i][j], AS, wmma::mem_row_major);
        __syncthreads();   // (C) S (fp32) staged

        // relu * 0.125, rowsum partial, split hi/lo in place; STS V
        {
            const int row = t >> 1;
            const int c0  = (t & 1) * 32;
#pragma unroll
            for (int u = 0; u < 8; ++u) {
                float4 s = *(const float4*)&sm[SHI + row * AS + c0 + 4 * u];
                s.x = fmaxf(s.x * 0.125f, 0.f);
                s.y = fmaxf(s.y * 0.125f, 0.f);
                s.z = fmaxf(s.z * 0.125f, 0.f);
                s.w = fmaxf(s.w * 0.125f, 0.f);
                dsum += s.x + s.y + s.z + s.w;
                float4 h, l;
                split4(s, h, l);
                *(float4*)&sm[SHI + row * AS + c0 + 4 * u] = h;
                *(float4*)&sm[SLO + row * AS + c0 + 4 * u] = l;
            }
        }
#pragma unroll
        for (int u = 0; u < 4; ++u) {
            float4 h, l;
            split4(vreg[u], h, l);
            *(float4*)&sm[VHI + kr * AS + kc + 4 * u] = h;
            *(float4*)&sm[VLO + kr * AS + kc + 4 * u] = l;
        }
        __syncthreads();   // (D) S(tf32) + V ready

        // ctx += S V  (3xTF32)
#pragma unroll
        for (int ks = 0; ks < 8; ++ks) {
            FragA shi[2], slo[2];
#pragma unroll
            for (int i = 0; i < 2; ++i) {
                wmma::load_matrix_sync(shi[i], sm + SHI + (wm + 16 * i) * AS + ks * 8, AS);
                wmma::load_matrix_sync(slo[i], sm + SLO + (wm + 16 * i) * AS + ks * 8, AS);
            }
#pragma unroll
            for (int j = 0; j < 2; ++j) {
                FragBr vhi, vlo;
                wmma::load_matrix_sync(vhi, sm + VHI + ks * 8 * AS + wn + 16 * j, AS);
                wmma::load_matrix_sync(vlo, sm + VLO + ks * 8 * AS + wn + 16 * j, AS);
#pragma unroll
                for (int i = 0; i < 2; ++i) {
                    wmma::mma_sync(ctx[i][j], shi[i], vhi, ctx[i][j]);
                    wmma::mma_sync(ctx[i][j], shi[i], vlo, ctx[i][j]);
                    wmma::mma_sync(ctx[i][j], slo[i], vhi, ctx[i][j]);
                }
            }
        }
    }

    __syncthreads();   // last SV-mma done; Q plane free for ctx scratch
    sm[DSO + t] = dsum;
#pragma unroll
    for (int i = 0; i < 2; ++i)
#pragma unroll
        for (int j = 0; j < 2; ++j)
            wmma::store_matrix_sync(&sm[QHI + (wm + 16 * i) * AS + wn + 16 * j],
                                    ctx[i][j], AS, wmma::mem_row_major);
    __syncthreads();

    {
        const int row = t >> 1;
        const int c0  = (t & 1) * 32;
        const float den = sm[DSO + 2 * row] + sm[DSO + 2 * row + 1];
        const float inv = 1.f / (den + 1e-6f);
        const int m = (tbh >> 3) * Nv + qn0 + row;
        float* dst = g_ctx + (size_t)m * Dv + (tbh & 7) * HDv + c0;
#pragma unroll
        for (int u = 0; u < 8; ++u) {
            float4 v = *(const float4*)&sm[QHI + row * AS + c0 + 4 * u];
            v.x *= inv; v.y *= inv; v.z *= inv; v.w *= inv;
            *(float4*)&dst[4 * u] = v;
        }
    }
}

// ---------------------------------------------------------------------------
extern "C" void kernel_launch(void* const* d_in, const int* in_sizes, int n_in,
                              void* d_out, int out_size)
{
    const float* x  = (const float*)d_in[0];
    const float* wq = (const float*)d_in[1];
    const float* bq = (const float*)d_in[2];
    const float* wk = (const float*)d_in[3];
    const float* bk = (const float*)d_in[4];
    const float* wv = (const float*)d_in[5];
    const float* bv = (const float*)d_in[6];
    const float* wo = (const float*)d_in[7];
    const float* bo = (const float*)d_in[8];
    float* out = (float*)d_out;

    cudaFuncSetAttribute(attn_w, cudaFuncAttributeMaxDynamicSharedMemorySize,
                         ATTN_SMEM_BYTES);

    qkv_gemm_w<<<dim3(Mv / 128, 12), 128, GEMM_SMEM_BYTES>>>(
        x, wq, bq, wk, bk, wv, bv);
    attn_w<<<dim3(Nv / 128, TBv * Hv), 256, ATTN_SMEM_BYTES>>>();
    out_gemm_w<<<dim3(Mv / 128, Dv / 128), 128, GEMM_SMEM_BYTES>>>(wo, bo, out);
}

// round 5
// speedup vs baseline: 3.7359x; 2.9761x over previous
#include <cuda_runtime.h>
#include <cuda_bf16.h>
#include <mma.h>
#include <cstdint>

using namespace nvcuda;

// Problem constants
#define TBv 16          // T*B
#define Nv  1024
#define Dv  512
#define Hv  8
#define HDv 64
#define Mv  (TBv * Nv)  // 16384 tokens

// Scratch: q,k,v head-major [TB][H][N][HD]; ctx token-major [M][D]
__device__ float g_q[TBv * Hv * Nv * HDv];
__device__ float g_k[TBv * Hv * Nv * HDv];
__device__ float g_v[TBv * Hv * Nv * HDv];
__device__ float g_ctx[(size_t)Mv * Dv];

// ---------------------------------------------------------------------------
// bf16 split helpers: x = hi + lo; hi*hi, hi*lo, lo*hi exact in fp32.
// ---------------------------------------------------------------------------
__device__ __forceinline__ void split_store4(float4 v,
                                             __nv_bfloat16* __restrict__ hp,
                                             __nv_bfloat16* __restrict__ lp)
{
    __nv_bfloat16 hx = __float2bfloat16_rn(v.x);
    __nv_bfloat16 hy = __float2bfloat16_rn(v.y);
    __nv_bfloat16 hz = __float2bfloat16_rn(v.z);
    __nv_bfloat16 hw = __float2bfloat16_rn(v.w);
    __nv_bfloat16 lx = __float2bfloat16_rn(v.x - __bfloat162float(hx));
    __nv_bfloat16 ly = __float2bfloat16_rn(v.y - __bfloat162float(hy));
    __nv_bfloat16 lz = __float2bfloat16_rn(v.z - __bfloat162float(hz));
    __nv_bfloat16 lw = __float2bfloat16_rn(v.w - __bfloat162float(hw));
    ((__nv_bfloat162*)hp)[0] = __halves2bfloat162(hx, hy);
    ((__nv_bfloat162*)hp)[1] = __halves2bfloat162(hz, hw);
    ((__nv_bfloat162*)lp)[0] = __halves2bfloat162(lx, ly);
    ((__nv_bfloat162*)lp)[1] = __halves2bfloat162(lz, lw);
}

using BFragA  = wmma::fragment<wmma::matrix_a, 16, 16, 16, __nv_bfloat16, wmma::row_major>;
using BFragBc = wmma::fragment<wmma::matrix_b, 16, 16, 16, __nv_bfloat16, wmma::col_major>;
using BFragBr = wmma::fragment<wmma::matrix_b, 16, 16, 16, __nv_bfloat16, wmma::row_major>;
using FragC   = wmma::fragment<wmma::accumulator, 16, 16, 16, float>;

// ===========================================================================
// GEMM: D[128x128] = A[128xK=512] . B[128 rows x 512]^T (+ bias via extra K)
// 256 threads, 8 warps (2m x 4n), warp tile 64x32 = 4x2 m16n16k16 frags.
// K-chunk 32 (2 bf16 ksteps). smem: hi/lo bf16 planes, stride 40 elems (80B).
// ===========================================================================
#define GSB 40
#define G_AHI 0
#define G_ALO (128 * GSB)
#define G_BHI (2 * 128 * GSB)
#define G_BLO (3 * 128 * GSB)
#define GEMM_SMEM_BYTES (4 * 128 * GSB * 2)   // 40960

__device__ __forceinline__ void gemm_kstep_bf(const __nv_bfloat16* __restrict__ sm,
                                              int ks, int wm, int wn,
                                              FragC (&acc)[4][2])
{
    BFragA ahi[4], alo[4];
#pragma unroll
    for (int i = 0; i < 4; ++i) {
        wmma::load_matrix_sync(ahi[i], sm + G_AHI + (wm + 16 * i) * GSB + ks * 16, GSB);
        wmma::load_matrix_sync(alo[i], sm + G_ALO + (wm + 16 * i) * GSB + ks * 16, GSB);
    }
#pragma unroll
    for (int j = 0; j < 2; ++j) {
        BFragBc bhi, blo;
        wmma::load_matrix_sync(bhi, sm + G_BHI + (wn + 16 * j) * GSB + ks * 16, GSB);
        wmma::load_matrix_sync(blo, sm + G_BLO + (wn + 16 * j) * GSB + ks * 16, GSB);
#pragma unroll
        for (int i = 0; i < 4; ++i) {
            wmma::mma_sync(acc[i][j], ahi[i], bhi, acc[i][j]);
            wmma::mma_sync(acc[i][j], ahi[i], blo, acc[i][j]);
            wmma::mma_sync(acc[i][j], alo[i], bhi, acc[i][j]);
        }
    }
}

__device__ __forceinline__ void gemm_block_bf(
    const float* __restrict__ Ag,    // 128 A rows, row-major stride 512
    const float* __restrict__ Bg,    // 128 W rows, row-major stride 512
    const float* __restrict__ bias,  // 128 bias entries
    __nv_bfloat16* __restrict__ sm, FragC (&acc)[4][2])
{
    const int tid = threadIdx.x;
    const int wid = tid >> 5;
    const int wm = (wid & 1) * 64;
    const int wn = (wid >> 1) * 32;
    const int r0 = tid >> 3;          // 0..31
    const int c4 = (tid & 7) * 4;     // 0..28

#pragma unroll
    for (int i = 0; i < 4; ++i)
#pragma unroll
        for (int j = 0; j < 2; ++j)
            wmma::fill_fragment(acc[i][j], 0.0f);

    for (int ch = 0; ch < 16; ++ch) {
        const int k0 = ch * 32;
        float4 ra[4], rb[4];
#pragma unroll
        for (int u = 0; u < 4; ++u) {
            ra[u] = *(const float4*)&Ag[(size_t)(r0 + 32 * u) * Dv + k0 + c4];
            rb[u] = *(const float4*)&Bg[(size_t)(r0 + 32 * u) * Dv + k0 + c4];
        }
        __syncthreads();   // previous chunk's mma reads done
#pragma unroll
        for (int u = 0; u < 4; ++u) {
            const int rr = (r0 + 32 * u) * GSB + c4;
            split_store4(ra[u], sm + G_AHI + rr, sm + G_ALO + rr);
            split_store4(rb[u], sm + G_BHI + rr, sm + G_BLO + rr);
        }
        __syncthreads();
        gemm_kstep_bf(sm, 0, wm, wn, acc);
        gemm_kstep_bf(sm, 1, wm, wn, acc);
    }

    // Bias as one extra K-step: A col0 = 1 (hi), B col0 = bias hi/lo.
    __syncthreads();
    if (tid < 128) {
        const int row = tid;
        const uint4 z = make_uint4(0, 0, 0, 0);
        *(uint4*)&sm[G_AHI + row * GSB]     = z;
        *(uint4*)&sm[G_AHI + row * GSB + 8] = z;
        *(uint4*)&sm[G_ALO + row * GSB]     = z;
        *(uint4*)&sm[G_ALO + row * GSB + 8] = z;
        *(uint4*)&sm[G_BHI + row * GSB]     = z;
        *(uint4*)&sm[G_BHI + row * GSB + 8] = z;
        *(uint4*)&sm[G_BLO + row * GSB]     = z;
        *(uint4*)&sm[G_BLO + row * GSB + 8] = z;
        const float bv = bias[row];
        const __nv_bfloat16 bh = __float2bfloat16_rn(bv);
        const __nv_bfloat16 bl = __float2bfloat16_rn(bv - __bfloat162float(bh));
        sm[G_AHI + row * GSB] = __float2bfloat16_rn(1.0f);
        sm[G_BHI + row * GSB] = bh;
        sm[G_BLO + row * GSB] = bl;
    }
    __syncthreads();
    gemm_kstep_bf(sm, 0, wm, wn, acc);
}

// ---------------------------------------------------------------------------
// QKV projection. grid (128, 12): y -> wsel(q/k/v) x 4 col-tiles of 128.
// ---------------------------------------------------------------------------
__global__ __launch_bounds__(256) void qkv_gemm_b(
    const float* __restrict__ x,
    const float* __restrict__ wq, const float* __restrict__ bq,
    const float* __restrict__ wk, const float* __restrict__ bk,
    const float* __restrict__ wv, const float* __restrict__ bv)
{
    extern __shared__ __nv_bfloat16 smb[];
    const int m0   = blockIdx.x * 128;
    const int wsel = blockIdx.y >> 2;
    const int n0   = (blockIdx.y & 3) * 128;

    const float* __restrict__ w    = (wsel == 0) ? wq : (wsel == 1) ? wk : wv;
    const float* __restrict__ bias = (wsel == 0) ? bq : (wsel == 1) ? bk : bv;
    float* __restrict__ obuf       = (wsel == 0) ? g_q : (wsel == 1) ? g_k : g_v;

    FragC acc[4][2];
    gemm_block_bf(x + (size_t)m0 * Dv, w + (size_t)n0 * Dv, bias + n0, smb, acc);

    const int wid = threadIdx.x >> 5;
    const int wm = (wid & 1) * 64;
    const int wn = (wid >> 1) * 32;
#pragma unroll
    for (int i = 0; i < 4; ++i) {
        const int m  = m0 + wm + 16 * i;
        const int tb = m >> 10;
        const int n  = m & 1023;
#pragma unroll
        for (int j = 0; j < 2; ++j) {
            const int col = n0 + wn + 16 * j;   // 16-col frag never crosses a head
            const int h   = col >> 6;
            const int hd0 = col & 63;
            wmma::store_matrix_sync(
                &obuf[((size_t)(tb * Hv + h) * Nv + n) * HDv + hd0],
                acc[i][j], HDv, wmma::mem_row_major);
        }
    }
}

// ---------------------------------------------------------------------------
// Output projection: out = ctx @ wo^T + bo. grid (128, 4).
// ---------------------------------------------------------------------------
__global__ __launch_bounds__(256) void out_gemm_b(
    const float* __restrict__ wo, const float* __restrict__ bo,
    float* __restrict__ out)
{
    extern __shared__ __nv_bfloat16 smb[];
    const int m0 = blockIdx.x * 128;
    const int n0 = blockIdx.y * 128;

    FragC acc[4][2];
    gemm_block_bf(g_ctx + (size_t)m0 * Dv, wo + (size_t)n0 * Dv, bo + n0, smb, acc);

    const int wid = threadIdx.x >> 5;
    const int wm = (wid & 1) * 64;
    const int wn = (wid >> 1) * 32;
#pragma unroll
    for (int i = 0; i < 4; ++i)
#pragma unroll
        for (int j = 0; j < 2; ++j)
            wmma::store_matrix_sync(
                &out[(size_t)(m0 + wm + 16 * i) * Dv + n0 + wn + 16 * j],
                acc[i][j], Dv, wmma::mem_row_major);
}

// ===========================================================================
// Attention via bf16 wmma (3xBF16).
// Block: 128 q-rows of one (tb,h); 256 threads, 8 warps (4m x 2n), warp 32x32.
// Loop 16 key-tiles of 64: S = QK^T -> relu/scale + rowsum -> hi/lo
// -> ctx += S V. Final: ctx / (rowsum + eps) -> g_ctx token-major.
// smem (bytes): Q planes 36864, K 18432, V 18432, Sfp32 34816,
//               S planes 36864, dsum 1024 = 146432.
// ===========================================================================
#define ASB 72                      // bf16 plane stride (elems)
#define SFS 68                      // fp32 S stride (elems)
#define O_QHI 0
#define O_QLO (O_QHI + 128 * ASB * 2)        // bytes
#define O_KHI (O_QLO + 128 * ASB * 2)
#define O_KLO (O_KHI + 64 * ASB * 2)
#define O_VHI (O_KLO + 64 * ASB * 2)
#define O_VLO (O_VHI + 64 * ASB * 2)
#define O_SFP (O_VLO + 64 * ASB * 2)
#define O_SHI (O_SFP + 128 * SFS * 4)
#define O_SLO (O_SHI + 128 * ASB * 2)
#define O_DS  (O_SLO + 128 * ASB * 2)
#define ATTN_SMEM_BYTES (O_DS + 256 * 4)     // 146432

__global__ __launch_bounds__(256) void attn_b()
{
    extern __shared__ char smc[];
    __nv_bfloat16* qhi = (__nv_bfloat16*)(smc + O_QHI);
    __nv_bfloat16* qlo = (__nv_bfloat16*)(smc + O_QLO);
    __nv_bfloat16* khi = (__nv_bfloat16*)(smc + O_KHI);
    __nv_bfloat16* klo = (__nv_bfloat16*)(smc + O_KLO);
    __nv_bfloat16* vhi = (__nv_bfloat16*)(smc + O_VHI);
    __nv_bfloat16* vlo = (__nv_bfloat16*)(smc + O_VLO);
    float*         sfp = (float*)(smc + O_SFP);
    __nv_bfloat16* shi = (__nv_bfloat16*)(smc + O_SHI);
    __nv_bfloat16* slo = (__nv_bfloat16*)(smc + O_SLO);
    float*         dso = (float*)(smc + O_DS);

    const int t = threadIdx.x;
    const int w = t >> 5;
    const int wm = (w >> 1) * 32;     // q-rows
    const int wn = (w & 1) * 32;      // key cols (S) / hd cols (ctx)
    const int qt  = blockIdx.x;
    const int tbh = blockIdx.y;
    const int qn0 = qt * 128;

    const float* __restrict__ qg = g_q + (size_t)tbh * Nv * HDv;
    const float* __restrict__ kg = g_k + (size_t)tbh * Nv * HDv;
    const float* __restrict__ vg = g_v + (size_t)tbh * Nv * HDv;

    // Load Q tile 128x64 -> hi/lo bf16 planes
    {
        const int row = t >> 1;
        const int c0  = (t & 1) * 32;
        const float* src = qg + (size_t)(qn0 + row) * HDv + c0;
#pragma unroll
        for (int u = 0; u < 8; ++u) {
            float4 v = *(const float4*)&src[u * 4];
            split_store4(v, qhi + row * ASB + c0 + 4 * u, qlo + row * ASB + c0 + 4 * u);
        }
    }

    FragC ctx[2][2];
#pragma unroll
    for (int i = 0; i < 2; ++i)
#pragma unroll
        for (int j = 0; j < 2; ++j)
            wmma::fill_fragment(ctx[i][j], 0.0f);
    float dsum = 0.f;

    const int kr = t >> 2;            // 0..63
    const int kc = (t & 3) * 16;

    for (int kt = 0; kt < 16; ++kt) {
        // stage K and V tiles (64x64) in registers (overlaps prev SV-mma)
        float4 kreg[4], vreg[4];
        {
            const float* ksrc = kg + (size_t)(kt * 64 + kr) * HDv + kc;
            const float* vsrc = vg + (size_t)(kt * 64 + kr) * HDv + kc;
#pragma unroll
            for (int u = 0; u < 4; ++u) {
                kreg[u] = *(const float4*)&ksrc[4 * u];
                vreg[u] = *(const float4*)&vsrc[4 * u];
            }
        }
        __syncthreads();   // (A) prev SV-mma reads done; Q visible (kt=0)
#pragma unroll
        for (int u = 0; u < 4; ++u)
            split_store4(kreg[u], khi + kr * ASB + kc + 4 * u, klo + kr * ASB + kc + 4 * u);
        __syncthreads();   // (B) K ready

        // S = Q K^T  (3xBF16), warp tile 32x32, 4 ksteps of 16
        FragC sacc[2][2];
#pragma unroll
        for (int i = 0; i < 2; ++i)
#pragma unroll
            for (int j = 0; j < 2; ++j)
                wmma::fill_fragment(sacc[i][j], 0.0f);
#pragma unroll
        for (int ks = 0; ks < 4; ++ks) {
            BFragA fqh[2], fql[2];
#pragma unroll
            for (int i = 0; i < 2; ++i) {
                wmma::load_matrix_sync(fqh[i], qhi + (wm + 16 * i) * ASB + ks * 16, ASB);
                wmma::load_matrix_sync(fql[i], qlo + (wm + 16 * i) * ASB + ks * 16, ASB);
            }
#pragma unroll
            for (int j = 0; j < 2; ++j) {
                BFragBc fkh, fkl;
                wmma::load_matrix_sync(fkh, khi + (wn + 16 * j) * ASB + ks * 16, ASB);
                wmma::load_matrix_sync(fkl, klo + (wn + 16 * j) * ASB + ks * 16, ASB);
#pragma unroll
                for (int i = 0; i < 2; ++i) {
                    wmma::mma_sync(sacc[i][j], fqh[i], fkh, sacc[i][j]);
                    wmma::mma_sync(sacc[i][j], fqh[i], fkl, sacc[i][j]);
                    wmma::mma_sync(sacc[i][j], fql[i], fkh, sacc[i][j]);
                }
            }
        }
#pragma unroll
        for (int i = 0; i < 2; ++i)
#pragma unroll
            for (int j = 0; j < 2; ++j)
                wmma::store_matrix_sync(&sfp[(wm + 16 * i) * SFS + wn + 16 * j],
                                        sacc[i][j], SFS, wmma::mem_row_major);
        __syncthreads();   // (C) S (fp32) staged

        // relu * 0.125, rowsum partial, split hi/lo; STS V planes
        {
            const int row = t >> 1;
            const int c0  = (t & 1) * 32;
#pragma unroll
            for (int u = 0; u < 8; ++u) {
                float4 s = *(const float4*)&sfp[row * SFS + c0 + 4 * u];
                s.x = fmaxf(s.x * 0.125f, 0.f);
                s.y = fmaxf(s.y * 0.125f, 0.f);
                s.z = fmaxf(s.z * 0.125f, 0.f);
                s.w = fmaxf(s.w * 0.125f, 0.f);
                dsum += s.x + s.y + s.z + s.w;
                split_store4(s, shi + row * ASB + c0 + 4 * u, slo + row * ASB + c0 + 4 * u);
            }
        }
#pragma unroll
        for (int u = 0; u < 4; ++u)
            split_store4(vreg[u], vhi + kr * ASB + kc + 4 * u, vlo + kr * ASB + kc + 4 * u);
        __syncthreads();   // (D) S(bf16) + V ready

        // ctx += S V  (3xBF16)
#pragma unroll
        for (int ks = 0; ks < 4; ++ks) {
            BFragA fsh[2], fsl[2];
#pragma unroll
            for (int i = 0; i < 2; ++i) {
                wmma::load_matrix_sync(fsh[i], shi + (wm + 16 * i) * ASB + ks * 16, ASB);
                wmma::load_matrix_sync(fsl[i], slo + (wm + 16 * i) * ASB + ks * 16, ASB);
            }
#pragma unroll
            for (int j = 0; j < 2; ++j) {
                BFragBr fvh, fvl;
                wmma::load_matrix_sync(fvh, vhi + ks * 16 * ASB + wn + 16 * j, ASB);
                wmma::load_matrix_sync(fvl, vlo + ks * 16 * ASB + wn + 16 * j, ASB);
#pragma unroll
                for (int i = 0; i < 2; ++i) {
                    wmma::mma_sync(ctx[i][j], fsh[i], fvh, ctx[i][j]);
                    wmma::mma_sync(ctx[i][j], fsh[i], fvl, ctx[i][j]);
                    wmma::mma_sync(ctx[i][j], fsl[i], fvh, ctx[i][j]);
                }
            }
        }
    }

    __syncthreads();   // all SV-mma done; Sfp32 free -> ctx scratch
    dso[t] = dsum;
#pragma unroll
    for (int i = 0; i < 2; ++i)
#pragma unroll
        for (int j = 0; j < 2; ++j)
            wmma::store_matrix_sync(&sfp[(wm + 16 * i) * SFS + wn + 16 * j],
                                    ctx[i][j], SFS, wmma::mem_row_major);
    __syncthreads();

    {
        const int row = t >> 1;
        const int c0  = (t & 1) * 32;
        const float den = dso[2 * row] + dso[2 * row + 1];
        const float inv = 1.f / (den + 1e-6f);
        const int m = (tbh >> 3) * Nv + qn0 + row;
        float* dst = g_ctx + (size_t)m * Dv + (tbh & 7) * HDv + c0;
#pragma unroll
        for (int u = 0; u < 8; ++u) {
            float4 v = *(const float4*)&sfp[row * SFS + c0 + 4 * u];
            v.x *= inv; v.y *= inv; v.z *= inv; v.w *= inv;
            *(float4*)&dst[4 * u] = v;
        }
    }
}

// ---------------------------------------------------------------------------
extern "C" void kernel_launch(void* const* d_in, const int* in_sizes, int n_in,
                              void* d_out, int out_size)
{
    const float* x  = (const float*)d_in[0];
    const float* wq = (const float*)d_in[1];
    const float* bq = (const float*)d_in[2];
    const float* wk = (const float*)d_in[3];
    const float* bk = (const float*)d_in[4];
    const float* wv = (const float*)d_in[5];
    const float* bv = (const float*)d_in[6];
    const float* wo = (const float*)d_in[7];
    const float* bo = (const float*)d_in[8];
    float* out = (float*)d_out;

    cudaFuncSetAttribute(attn_b, cudaFuncAttributeMaxDynamicSharedMemorySize,
                         ATTN_SMEM_BYTES);

    qkv_gemm_b<<<dim3(Mv / 128, 12), 256, GEMM_SMEM_BYTES>>>(
        x, wq, bq, wk, bk, wv, bv);
    attn_b<<<dim3(Nv / 128, TBv * Hv), 256, ATTN_SMEM_BYTES>>>();
    out_gemm_b<<<dim3(Mv / 128, Dv / 128), 256, GEMM_SMEM_BYTES>>>(wo, bo, out);
}